// round 8
// baseline (speedup 1.0000x reference)
#include <cuda_runtime.h>

#define R_N 1000
#define C_N 81
#define NC  80
#define NEGV (-1e9f)
#define SCORE_T 0.05f
#define IOU_T 0.5f
#define TOPK 100
#define GRID 8
#define BLOCK 1024
#define CPB (NC / GRID)      // 10 classes per block
#define CANDMAX 192

// ---------------- device scratch (no allocations allowed) ----------------
__device__ int g_cnt[NC];                          // per-class pre-NMS counts
__device__ unsigned long long g_clist[NC * R_N];   // per-class key lists
__device__ unsigned long long g_pool[NC * R_N];    // post-NMS survivor keys
__device__ float4 g_pbox[NC * R_N];                // survivor boxes by flat idx
__device__ int g_count;
__device__ int g_c1, g_c2;                         // barrier counters

// ---------------- helpers ----------------
__device__ __forceinline__ unsigned int ord32(float f) {
    unsigned int u = __float_as_uint(f);
    return (u & 0x80000000u) ? ~u : (u | 0x80000000u);
}
__device__ __forceinline__ float unord32(unsigned int u) {
    unsigned int b = (u & 0x80000000u) ? (u ^ 0x80000000u) : ~u;
    return __uint_as_float(b);
}
__device__ __forceinline__ float load_dim(const void* p) {
    int iv = *(const int*)p;
    if (iv > 0 && iv < 1000000) return (float)iv;
    return *(const float*)p;
}
__device__ __forceinline__ void push_key(int c, int row, float prob) {
    if (prob > SCORE_T) {
        int slot = atomicAdd(&g_cnt[c - 1], 1);
        g_clist[(c - 1) * R_N + slot] =
            ((unsigned long long)ord32(prob) << 32) | (unsigned int)(~row);
    }
}

__device__ __forceinline__ float4 decode_box(const float4* __restrict__ props4,
                                             const float4* __restrict__ reg4,
                                             int r, int c, float W, float H) {
    const float CLIPV = 4.135166556742356f;   // log(1000/16)
    float4 p = props4[r];
    float bw = p.z - p.x + 1.f, bh = p.w - p.y + 1.f;
    float cx = p.x + 0.5f * bw,  cy = p.y + 0.5f * bh;
    float4 rr = reg4[(size_t)r * C_N + c];
    float dx = rr.x / 10.0f;
    float dy = rr.y / 10.0f;
    float dw = fminf(rr.z / 5.0f, CLIPV);
    float dh = fminf(rr.w / 5.0f, CLIPV);
    float pcx = dx * bw + cx;
    float pcy = dy * bh + cy;
    float pw2 = expf(dw) * bw;
    float ph2 = expf(dh) * bh;
    float x1 = fminf(fmaxf(pcx - 0.5f * pw2, 0.f), W - 1.f);
    float y1 = fminf(fmaxf(pcy - 0.5f * ph2, 0.f), H - 1.f);
    float x2 = fminf(fmaxf(pcx + 0.5f * pw2 - 1.f, 0.f), W - 1.f);
    float y2 = fminf(fmaxf(pcy + 0.5f * ph2 - 1.f, 0.f), H - 1.f);
    return make_float4(x1, y1, x2, y2);
}

// exact IoU-suppression test (same op order as validated rounds)
__device__ __forceinline__ bool sup_test(float4 b, float A, const float* q) {
    float ix1 = fmaxf(b.x, q[0]), iy1 = fmaxf(b.y, q[1]);
    float ix2 = fminf(b.z, q[2]), iy2 = fminf(b.w, q[3]);
    float iw = fmaxf(ix2 - ix1 + 1.f, 0.f);
    float ih = fmaxf(iy2 - iy1 + 1.f, 0.f);
    float inter = iw * ih;
    return inter / (A + q[4] - inter) > IOU_T;
}

// shared scratch union (phases temporally disjoint)
union Scratch {
    struct {                                 // phase B fast path (per-warp slices)
        float box[CPB][64][5];
        unsigned long long mask[CPB][64];
    } nms;
    struct {                                 // phase B fallback (block-wide, rare)
        unsigned long long skey[1024];
        float bx[5][1024];
        unsigned char rem[1024];
    } fb;
    struct {                                 // phase C
        int hist[2048];
        unsigned long long cand[512];
    } sel;
};

__device__ void bitonic_desc(unsigned long long* a, int n) {
    for (unsigned int k = 2; k <= (unsigned int)n; k <<= 1) {
        for (unsigned int j = k >> 1; j > 0; j >>= 1) {
            for (unsigned int i = threadIdx.x; i < (unsigned int)n; i += BLOCK) {
                unsigned int l = i ^ j;
                if (l > i) {
                    unsigned long long x = a[i], y = a[l];
                    bool up = ((i & k) == 0);
                    if (up ? (x < y) : (x > y)) { a[i] = y; a[l] = x; }
                }
            }
            __syncthreads();
        }
    }
}

__global__ void __launch_bounds__(BLOCK) k_fused(
        const float* __restrict__ logits,
        const float* __restrict__ reg,
        const float* __restrict__ props,
        const void* pw, const void* ph,
        float* __restrict__ out) {

    __shared__ Scratch u;
    __shared__ int wtot[32];
    __shared__ int s_ovf[CPB];
    __shared__ int s_novf, s_cnt, s_thr, s_tot, s_d, s_cum, s_bin;

    int tid = threadIdx.x;
    int wid = tid >> 5;
    int lane = tid & 31;
    const float4* props4 = (const float4*)props;
    const float4* reg4 = (const float4*)reg;
    float W = load_dim(pw), H = load_dim(ph);

    if (tid == 0) s_novf = 0;

    // ---------- Phase A: softmax + filter + per-class push (4 rows per warp) ----------
    {
        int gw = blockIdx.x * (BLOCK / 32) + wid;    // 0..255
        #pragma unroll
        for (int q = 0; q < 4; q++) {
            int row = gw * 4 + q;
            if (row < R_N) {
                const float* lg = logits + (size_t)row * C_N;
                float a = (lane      < C_N) ? lg[lane]      : -INFINITY;
                float b = (lane + 32 < C_N) ? lg[lane + 32] : -INFINITY;
                float d = (lane + 64 < C_N) ? lg[lane + 64] : -INFINITY;
                float m = fmaxf(a, fmaxf(b, d));
                for (int o = 16; o; o >>= 1) m = fmaxf(m, __shfl_xor_sync(0xffffffffu, m, o));
                float ea = (lane      < C_N) ? expf(a - m) : 0.f;
                float eb = (lane + 32 < C_N) ? expf(b - m) : 0.f;
                float ed = (lane + 64 < C_N) ? expf(d - m) : 0.f;
                float s = ea + eb + ed;
                for (int o = 16; o; o >>= 1) s += __shfl_xor_sync(0xffffffffu, s, o);
                float inv = 1.f / s;
                if (lane >= 1)  push_key(lane,      row, ea * inv);   // c = 1..31
                push_key(lane + 32, row, eb * inv);                   // c = 32..63
                if (lane <= 16) push_key(lane + 64, row, ed * inv);   // c = 64..80
            }
        }
    }
    __syncthreads();
    __threadfence();
    if (tid == 0) {
        atomicAdd(&g_c1, 1);
        while (*(volatile int*)&g_c1 < GRID) __nanosleep(32);
    }
    __syncthreads();
    __threadfence();

    // ---------- Phase B: one warp per class, warp-local NMS ----------
    int c0 = blockIdx.x * CPB + wid;    // valid for wid < CPB
    int M = (wid < CPB) ? *(volatile int*)&g_cnt[c0] : 0;

    if (wid < CPB && M > 64) {
        if (lane == 0) { int p = atomicAdd(&s_novf, 1); s_ovf[p] = c0; }
    }
    if (wid < CPB && M > 0 && M <= 64) {
        const unsigned long long* list = g_clist + (size_t)c0 * R_N;
        unsigned long long k0 = (lane < M)      ? __ldcg(&list[lane])      : 0ULL;
        unsigned long long k1 = (lane + 32 < M) ? __ldcg(&list[lane + 32]) : 0ULL;
        int r0 = 0, r1 = 0;
        for (int j = 0; j < M; j++) {
            unsigned long long kj = (j < 32) ? __shfl_sync(0xffffffffu, k0, j)
                                             : __shfl_sync(0xffffffffu, k1, j - 32);
            r0 += (kj > k0);
            r1 += (kj > k1);
        }
        float4 b0 = make_float4(0, 0, 0, 0), b1 = make_float4(0, 0, 0, 0);
        float A0 = 0.f, A1 = 0.f;
        if (lane < M) {
            int r = (int)(~(unsigned int)k0);
            b0 = decode_box(props4, reg4, r, c0 + 1, W, H);
            A0 = (b0.z - b0.x + 1.f) * (b0.w - b0.y + 1.f);
            float* d = u.nms.box[wid][r0];
            d[0] = b0.x; d[1] = b0.y; d[2] = b0.z; d[3] = b0.w; d[4] = A0;
        }
        if (lane + 32 < M) {
            int r = (int)(~(unsigned int)k1);
            b1 = decode_box(props4, reg4, r, c0 + 1, W, H);
            A1 = (b1.z - b1.x + 1.f) * (b1.w - b1.y + 1.f);
            float* d = u.nms.box[wid][r1];
            d[0] = b1.x; d[1] = b1.y; d[2] = b1.z; d[3] = b1.w; d[4] = A1;
        }
        __syncwarp();
        if (lane < M) {
            unsigned long long msk = 0ULL;
            for (int j = r0 + 1; j < M; j++)
                if (sup_test(b0, A0, u.nms.box[wid][j])) msk |= (1ULL << j);
            u.nms.mask[wid][r0] = msk;
        }
        if (lane + 32 < M) {
            unsigned long long msk = 0ULL;
            for (int j = r1 + 1; j < M; j++)
                if (sup_test(b1, A1, u.nms.box[wid][j])) msk |= (1ULL << j);
            u.nms.mask[wid][r1] = msk;
        }
        __syncwarp();
        unsigned long long removed = 0ULL, keep = 0ULL;
        for (int i = 0; i < M; i++) {            // uniform across warp
            if (!((removed >> i) & 1ULL)) {
                keep |= (1ULL << i);
                removed |= u.nms.mask[wid][i];
            }
        }
        if (lane < M && ((keep >> r0) & 1ULL)) {
            unsigned int flat = (unsigned int)(c0 * R_N) + (~(unsigned int)k0);
            int p = atomicAdd(&g_count, 1);
            g_pool[p] = (k0 & 0xffffffff00000000ULL) | (unsigned int)(~flat);
            g_pbox[flat] = b0;
        }
        if (lane + 32 < M && ((keep >> r1) & 1ULL)) {
            unsigned int flat = (unsigned int)(c0 * R_N) + (~(unsigned int)k1);
            int p = atomicAdd(&g_count, 1);
            g_pool[p] = (k1 & 0xffffffff00000000ULL) | (unsigned int)(~flat);
            g_pbox[flat] = b1;
        }
    }
    __syncthreads();

    // rare fallback: block-wide greedy for classes with M > 64
    int novf = s_novf;
    for (int oi = 0; oi < novf; oi++) {
        int cc0 = s_ovf[oi];
        int Mf = *(volatile int*)&g_cnt[cc0];
        if (Mf > 1024) Mf = 1024;
        for (int i = tid; i < Mf; i += BLOCK) u.fb.skey[i] = __ldcg(&g_clist[(size_t)cc0 * R_N + i]);
        int n = 1; while (n < Mf) n <<= 1;
        for (int i = Mf + tid; i < n; i += BLOCK) u.fb.skey[i] = 0ULL;
        __syncthreads();
        bitonic_desc(u.fb.skey, n);
        for (int i = tid; i < Mf; i += BLOCK) {
            int r = (int)(~(unsigned int)u.fb.skey[i]);
            float4 b = decode_box(props4, reg4, r, cc0 + 1, W, H);
            u.fb.bx[0][i] = b.x; u.fb.bx[1][i] = b.y; u.fb.bx[2][i] = b.z; u.fb.bx[3][i] = b.w;
            u.fb.bx[4][i] = (b.z - b.x + 1.f) * (b.w - b.y + 1.f);
            u.fb.rem[i] = 0;
        }
        __syncthreads();
        for (int i = 0; i < Mf; i++) {
            if (!u.fb.rem[i]) {
                float X1 = u.fb.bx[0][i], Y1 = u.fb.bx[1][i], X2 = u.fb.bx[2][i], Y2 = u.fb.bx[3][i];
                float A = u.fb.bx[4][i];
                for (int j = i + 1 + tid; j < Mf; j += BLOCK) {
                    if (!u.fb.rem[j]) {
                        float ix1 = fmaxf(X1, u.fb.bx[0][j]), iy1 = fmaxf(Y1, u.fb.bx[1][j]);
                        float ix2 = fminf(X2, u.fb.bx[2][j]), iy2 = fminf(Y2, u.fb.bx[3][j]);
                        float iw = fmaxf(ix2 - ix1 + 1.f, 0.f);
                        float ih = fmaxf(iy2 - iy1 + 1.f, 0.f);
                        float inter = iw * ih;
                        if (inter / (A + u.fb.bx[4][j] - inter) > IOU_T) u.fb.rem[j] = 1;
                    }
                }
            }
            __syncthreads();
        }
        for (int i = tid; i < Mf; i += BLOCK) {
            if (!u.fb.rem[i]) {
                unsigned long long kk = u.fb.skey[i];
                unsigned int flat = (unsigned int)(cc0 * R_N) + (~(unsigned int)kk);
                int p = atomicAdd(&g_count, 1);
                g_pool[p] = (kk & 0xffffffff00000000ULL) | (unsigned int)(~flat);
                g_pbox[flat] = make_float4(u.fb.bx[0][i], u.fb.bx[1][i], u.fb.bx[2][i], u.fb.bx[3][i]);
            }
        }
        __syncthreads();
    }

    // ---------- barrier 2: block 0 proceeds to phase C ----------
    __syncthreads();
    __threadfence();
    if (tid == 0) atomicAdd(&g_c2, 1);
    if (blockIdx.x != 0) return;
    if (tid == 0) { while (*(volatile int*)&g_c2 < GRID) __nanosleep(32); }
    __syncthreads();
    __threadfence();

    // ---------- Phase C: shared-hist threshold + rank placement ----------
    int K = *(volatile int*)&g_count;
    bool takeAll = (K <= 512);
    bool fastSel = false;
    int thr = 0;
    unsigned long long prefix = 0;
    int shift = 56;

    if (takeAll) {
        for (int i = tid; i < K; i += BLOCK) u.sel.cand[i] = __ldcg(&g_pool[i]);
        if (tid == 0) s_cnt = K;
        __syncthreads();
    } else {
        u.sel.hist[2 * tid] = 0; u.sel.hist[2 * tid + 1] = 0;
        __syncthreads();
        for (int i = tid; i < K; i += BLOCK)
            atomicAdd(&u.sel.hist[(int)(__ldcg(&g_pool[i]) >> 51) & 2047], 1);
        __syncthreads();
        // 3-barrier suffix scan: bin index ascending == score ascending (monotonic for scores in (0.05, 1])
        int h0 = u.sel.hist[2 * tid], h1 = u.sel.hist[2 * tid + 1];
        int v = h0 + h1;
        for (int off = 1; off < 32; off <<= 1) {
            int nv = __shfl_down_sync(0xffffffffu, v, off);
            if (lane + off < 32) v += nv;
        }
        if (lane == 0) wtot[wid] = v;
        __syncthreads();
        if (wid == 0) {
            int w = wtot[lane];
            for (int off = 1; off < 32; off <<= 1) {
                int nw = __shfl_down_sync(0xffffffffu, w, off);
                if (lane + off < 32) w += nw;
            }
            wtot[lane] = w;   // suffix over warps lane..31
        }
        __syncthreads();
        int S = v + ((wid < 31) ? wtot[wid + 1] : 0);   // keys in bins >= 2*tid
        int cge1 = S - h0;             // cnt >= bin 2t+1  (== cnt > bin 2t)
        int cgt1 = cge1 - h1;          // cnt >  bin 2t+1
        if (cgt1 < TOPK && cge1 >= TOPK) { s_thr = 2 * tid + 1; s_tot = cge1; }
        if (cge1 < TOPK && S >= TOPK)    { s_thr = 2 * tid;     s_tot = S; }
        __syncthreads();
        thr = s_thr;
        fastSel = (s_tot <= 512);

        if (!fastSel) {
            // rare: boundary bin too fat — adaptive 64-bit radix descent (reuses hist[0..255])
            int needed = TOPK;
            for (;;) {
                for (int i = tid; i < 256; i += BLOCK) u.sel.hist[i] = 0;
                __syncthreads();
                for (int i = tid; i < K; i += BLOCK) {
                    unsigned long long k = __ldcg(&g_pool[i]);
                    bool act = (shift == 56) || ((k >> (shift + 8)) == prefix);
                    if (act) atomicAdd(&u.sel.hist[(int)((k >> shift) & 255)], 1);
                }
                __syncthreads();
                if (tid == 0) {
                    int cum = 0, d;
                    for (d = 255; d > 0; d--) {
                        int h = u.sel.hist[d];
                        if (cum + h >= needed) break;
                        cum += h;
                    }
                    s_d = d; s_cum = cum; s_bin = u.sel.hist[d];
                }
                __syncthreads();
                needed -= s_cum;
                prefix = (prefix << 8) | (unsigned int)s_d;
                int binCount = s_bin;
                shift -= 8;
                if ((TOPK - needed) + binCount <= CANDMAX || shift < 0) break;
                __syncthreads();
            }
        }
        if (tid == 0) s_cnt = 0;
        __syncthreads();
        int sh = shift + 8;
        for (int i = tid; i < K; i += BLOCK) {
            unsigned long long k = __ldcg(&g_pool[i]);
            bool take = fastSel ? (((int)(k >> 51) & 2047) >= thr)
                                : ((k >> sh) >= prefix);
            if (take) {
                int p = atomicAdd(&s_cnt, 1);
                if (p < 512) u.sel.cand[p] = k;
            }
        }
        __syncthreads();
    }
    int count = min(s_cnt, 512);

    for (int i = tid; i < count; i += BLOCK) {
        unsigned long long kk = u.sel.cand[i];
        int rank = 0;
        for (int j = 0; j < count; j++) rank += (u.sel.cand[j] > kk);
        if (rank < TOPK) {
            unsigned int flat = ~(unsigned int)(kk & 0xffffffffu);
            float score = unord32((unsigned int)(kk >> 32));
            int cc = flat / R_N;
            float4 b = __ldcg(&g_pbox[flat]);
            out[rank] = score;
            out[TOPK + 4 * rank + 0] = b.x;
            out[TOPK + 4 * rank + 1] = b.y;
            out[TOPK + 4 * rank + 2] = b.z;
            out[TOPK + 4 * rank + 3] = b.w;
            out[5 * TOPK + rank] = (float)(cc + 1);
        }
    }
    if (count < TOPK && tid == 0) {
        int p = count;
        for (int f = 0; p < TOPK; f++) {
            bool used = false;
            for (int q = 0; q < count; q++) {
                unsigned int fl = ~(unsigned int)(u.sel.cand[q] & 0xffffffffu);
                if ((int)fl == f) { used = true; break; }
            }
            if (!used) {
                int cc = f / R_N;
                int r = f - cc * R_N;
                float4 b = decode_box(props4, reg4, r, cc + 1, W, H);
                out[p] = NEGV;
                out[TOPK + 4 * p + 0] = b.x;
                out[TOPK + 4 * p + 1] = b.y;
                out[TOPK + 4 * p + 2] = b.z;
                out[TOPK + 4 * p + 3] = b.w;
                out[5 * TOPK + p] = (float)(cc + 1);
                p++;
            }
        }
    }

    // reset scratch for next graph replay (only block 0 alive)
    __syncthreads();
    if (tid < NC) g_cnt[tid] = 0;
    if (tid == 0) { g_c1 = 0; g_c2 = 0; g_count = 0; }
    __threadfence();
}

// ---------------- launch ----------------
extern "C" void kernel_launch(void* const* d_in, const int* in_sizes, int n_in,
                              void* d_out, int out_size) {
    const float *logits = nullptr, *reg = nullptr, *props = nullptr;
    const void *pw = nullptr, *ph = nullptr;
    for (int i = 0; i < n_in; i++) {
        int s = in_sizes[i];
        if (s == R_N * C_N)            logits = (const float*)d_in[i];
        else if (s == R_N * C_N * 4)   reg    = (const float*)d_in[i];
        else if (s == R_N * 4)         props  = (const float*)d_in[i];
        else if (s == 1) { if (!pw) pw = d_in[i]; else ph = d_in[i]; }
    }
    k_fused<<<GRID, BLOCK>>>(logits, reg, props, pw, ph, (float*)d_out);
}

// round 9
// speedup vs baseline: 1.1175x; 1.1175x over previous
#include <cuda_runtime.h>

#define R_N 1000
#define C_N 81
#define NC  80
#define NEGV (-1e9f)
#define SCORE_T 0.05f
#define IOU_T 0.5f
#define TOPK 100
#define GRID NC
#define BLOCK 512
#define SELCAP 2048
#define CANDMAX 1024

// ---------------- device scratch (no allocations allowed) ----------------
__device__ int g_cnt[NC];                          // per-class pre-NMS counts
__device__ unsigned long long g_clist[NC * R_N];   // per-class key lists (slot order)
__device__ float4 g_cbox[NC * R_N];                // decoded boxes (slot order)
__device__ unsigned long long g_pool[NC * R_N];    // post-NMS survivor keys
__device__ float4 g_pbox[NC * R_N];                // survivor boxes by flat idx
__device__ int g_count;
__device__ int g_c1, g_c2;                         // barrier / ticket counters

// ---------------- helpers ----------------
__device__ __forceinline__ unsigned int ord32(float f) {
    unsigned int u = __float_as_uint(f);
    return (u & 0x80000000u) ? ~u : (u | 0x80000000u);
}
__device__ __forceinline__ float unord32(unsigned int u) {
    unsigned int b = (u & 0x80000000u) ? (u ^ 0x80000000u) : ~u;
    return __uint_as_float(b);
}
__device__ __forceinline__ float load_dim(const void* p) {
    int iv = *(const int*)p;
    if (iv > 0 && iv < 1000000) return (float)iv;
    return *(const float*)p;
}
// monotonic 11-bit bin for positive scores < 2.0 (bit62 of key is 0)
__device__ __forceinline__ int kbin(unsigned long long k) {
    return (int)(k >> 51) & (SELCAP - 1);
}

__device__ __forceinline__ float4 decode_box(const float4* __restrict__ props4,
                                             const float4* __restrict__ reg4,
                                             int r, int c, float W, float H) {
    const float CLIPV = 4.135166556742356f;   // log(1000/16)
    float4 p = props4[r];
    float bw = p.z - p.x + 1.f, bh = p.w - p.y + 1.f;
    float cx = p.x + 0.5f * bw,  cy = p.y + 0.5f * bh;
    float4 rr = reg4[(size_t)r * C_N + c];
    float dx = rr.x / 10.0f;
    float dy = rr.y / 10.0f;
    float dw = fminf(rr.z / 5.0f, CLIPV);
    float dh = fminf(rr.w / 5.0f, CLIPV);
    float pcx = dx * bw + cx;
    float pcy = dy * bh + cy;
    float pw2 = expf(dw) * bw;
    float ph2 = expf(dh) * bh;
    float x1 = fminf(fmaxf(pcx - 0.5f * pw2, 0.f), W - 1.f);
    float y1 = fminf(fmaxf(pcy - 0.5f * ph2, 0.f), H - 1.f);
    float x2 = fminf(fmaxf(pcx + 0.5f * pw2 - 1.f, 0.f), W - 1.f);
    float y2 = fminf(fmaxf(pcy + 0.5f * ph2 - 1.f, 0.f), H - 1.f);
    return make_float4(x1, y1, x2, y2);
}

__device__ __forceinline__ bool sup_test(float4 b, float A, const float* q) {
    float ix1 = fmaxf(b.x, q[0]), iy1 = fmaxf(b.y, q[1]);
    float ix2 = fminf(b.z, q[2]), iy2 = fminf(b.w, q[3]);
    float iw = fmaxf(ix2 - ix1 + 1.f, 0.f);
    float ih = fmaxf(iy2 - iy1 + 1.f, 0.f);
    float inter = iw * ih;
    return inter / (A + q[4] - inter) > IOU_T;
}

// shared scratch (phases temporally disjoint)
union Scratch {
    struct {                                  // phase B fast (warp 0 only)
        float box[64][5];
        unsigned long long mask[64];
    } w;
    struct {                                  // phase B fallback (rare)
        unsigned long long skey[1024];
        float bx[5][1024];
        unsigned char rem[1024];
    } fb;
    struct {                                  // phase C
        unsigned long long cand[SELCAP];
        int hist[SELCAP];
        unsigned long long sel[SELCAP];
    } c;
};

__device__ void bitonic_desc(unsigned long long* a, int n) {
    for (unsigned int k = 2; k <= (unsigned int)n; k <<= 1) {
        for (unsigned int j = k >> 1; j > 0; j >>= 1) {
            for (unsigned int i = threadIdx.x; i < (unsigned int)n; i += BLOCK) {
                unsigned int l = i ^ j;
                if (l > i) {
                    unsigned long long x = a[i], y = a[l];
                    bool up = ((i & k) == 0);
                    if (up ? (x < y) : (x > y)) { a[i] = y; a[l] = x; }
                }
            }
            __syncthreads();
        }
    }
}

__global__ void __launch_bounds__(BLOCK) k_fused(
        const float* __restrict__ logits,
        const float* __restrict__ reg,
        const float* __restrict__ props,
        const void* pw, const void* ph,
        float* __restrict__ out) {

    __shared__ Scratch u;
    __shared__ int wtot[16];
    __shared__ int s_cnt, s_thr, s_tot, s_doC, s_d, s_cum, s_bin;

    int tid = threadIdx.x;
    int wid = tid >> 5;
    int lane = tid & 31;
    const float4* props4 = (const float4*)props;
    const float4* reg4 = (const float4*)reg;
    float W = load_dim(pw), H = load_dim(ph);

    // ---------- Phase A: softmax + filter + key push + EAGER decode ----------
    {
        int row = wid * 80 + blockIdx.x;   // 12-13 rows per block, balanced
        if (row < R_N) {
            const float* lg = logits + (size_t)row * C_N;
            float a = (lane      < C_N) ? lg[lane]      : -INFINITY;
            float b = (lane + 32 < C_N) ? lg[lane + 32] : -INFINITY;
            float d = (lane + 64 < C_N) ? lg[lane + 64] : -INFINITY;
            float m = fmaxf(a, fmaxf(b, d));
            for (int o = 16; o; o >>= 1) m = fmaxf(m, __shfl_xor_sync(0xffffffffu, m, o));
            float ea = (lane      < C_N) ? expf(a - m) : 0.f;
            float eb = (lane + 32 < C_N) ? expf(b - m) : 0.f;
            float ed = (lane + 64 < C_N) ? expf(d - m) : 0.f;
            float s = ea + eb + ed;
            for (int o = 16; o; o >>= 1) s += __shfl_xor_sync(0xffffffffu, s, o);
            float inv = 1.f / s;

            #pragma unroll
            for (int q = 0; q < 3; q++) {
                int c = lane + q * 32;               // logit index == class
                float e = (q == 0) ? ea : (q == 1) ? eb : ed;
                if (c >= 1 && c <= NC) {
                    float prob = e * inv;
                    if (prob > SCORE_T) {
                        int slot = atomicAdd(&g_cnt[c - 1], 1);
                        g_clist[(c - 1) * R_N + slot] =
                            ((unsigned long long)ord32(prob) << 32) | (unsigned int)(~row);
                        g_cbox[(c - 1) * R_N + slot] = decode_box(props4, reg4, row, c, W, H);
                    }
                }
            }
        }
    }
    __syncthreads();
    __threadfence();
    if (tid == 0) {
        atomicAdd(&g_c1, 1);
        while (*(volatile int*)&g_c1 < GRID) __nanosleep(32);
    }
    __syncthreads();
    __threadfence();

    // ---------- Phase B: one class per block; warp 0 does warp-local NMS ----------
    int c0 = blockIdx.x;
    int M = *(volatile int*)&g_cnt[c0];

    if (M > 0 && M <= 64) {
        if (wid == 0) {
            const unsigned long long* list = g_clist + (size_t)c0 * R_N;
            const float4* boxes = g_cbox + (size_t)c0 * R_N;
            unsigned long long k0 = (lane < M)      ? __ldcg(&list[lane])      : 0ULL;
            unsigned long long k1 = (lane + 32 < M) ? __ldcg(&list[lane + 32]) : 0ULL;
            int r0 = 0, r1 = 0;
            for (int j = 0; j < M; j++) {
                unsigned long long kj = (j < 32) ? __shfl_sync(0xffffffffu, k0, j)
                                                 : __shfl_sync(0xffffffffu, k1, j - 32);
                r0 += (kj > k0);
                r1 += (kj > k1);
            }
            float4 b0 = make_float4(0,0,0,0), b1 = make_float4(0,0,0,0);
            float A0 = 0.f, A1 = 0.f;
            if (lane < M) {
                b0 = boxes[lane];
                A0 = (b0.z - b0.x + 1.f) * (b0.w - b0.y + 1.f);
                float* dst = u.w.box[r0];
                dst[0] = b0.x; dst[1] = b0.y; dst[2] = b0.z; dst[3] = b0.w; dst[4] = A0;
            }
            if (lane + 32 < M) {
                b1 = boxes[lane + 32];
                A1 = (b1.z - b1.x + 1.f) * (b1.w - b1.y + 1.f);
                float* dst = u.w.box[r1];
                dst[0] = b1.x; dst[1] = b1.y; dst[2] = b1.z; dst[3] = b1.w; dst[4] = A1;
            }
            __syncwarp();
            if (lane < M) {
                unsigned long long msk = 0ULL;
                for (int j = r0 + 1; j < M; j++)
                    if (sup_test(b0, A0, u.w.box[j])) msk |= (1ULL << j);
                u.w.mask[r0] = msk;
            }
            if (lane + 32 < M) {
                unsigned long long msk = 0ULL;
                for (int j = r1 + 1; j < M; j++)
                    if (sup_test(b1, A1, u.w.box[j])) msk |= (1ULL << j);
                u.w.mask[r1] = msk;
            }
            __syncwarp();
            unsigned long long removed = 0ULL, keep = 0ULL;
            for (int i = 0; i < M; i++) {          // uniform across warp
                if (!((removed >> i) & 1ULL)) {
                    keep |= (1ULL << i);
                    removed |= u.w.mask[i];
                }
            }
            if (lane < M && ((keep >> r0) & 1ULL)) {
                unsigned int flat = (unsigned int)(c0 * R_N) + (~(unsigned int)k0);
                int p = atomicAdd(&g_count, 1);
                g_pool[p] = (k0 & 0xffffffff00000000ULL) | (unsigned int)(~flat);
                g_pbox[flat] = b0;
            }
            if (lane + 32 < M && ((keep >> r1) & 1ULL)) {
                unsigned int flat = (unsigned int)(c0 * R_N) + (~(unsigned int)k1);
                int p = atomicAdd(&g_count, 1);
                g_pool[p] = (k1 & 0xffffffff00000000ULL) | (unsigned int)(~flat);
                g_pbox[flat] = b1;
            }
        }
    } else if (M > 64) {
        // rare fallback: block-wide sorted greedy
        int Mf = min(M, 1024);
        for (int i = tid; i < Mf; i += BLOCK) u.fb.skey[i] = __ldcg(&g_clist[(size_t)c0 * R_N + i]);
        int n = 1; while (n < Mf) n <<= 1;
        for (int i = Mf + tid; i < n; i += BLOCK) u.fb.skey[i] = 0ULL;
        __syncthreads();
        bitonic_desc(u.fb.skey, n);
        for (int i = tid; i < Mf; i += BLOCK) {
            int r = (int)(~(unsigned int)u.fb.skey[i]);
            float4 b = decode_box(props4, reg4, r, c0 + 1, W, H);
            u.fb.bx[0][i] = b.x; u.fb.bx[1][i] = b.y; u.fb.bx[2][i] = b.z; u.fb.bx[3][i] = b.w;
            u.fb.bx[4][i] = (b.z - b.x + 1.f) * (b.w - b.y + 1.f);
            u.fb.rem[i] = 0;
        }
        __syncthreads();
        for (int i = 0; i < Mf; i++) {
            if (!u.fb.rem[i]) {
                float X1 = u.fb.bx[0][i], Y1 = u.fb.bx[1][i], X2 = u.fb.bx[2][i], Y2 = u.fb.bx[3][i];
                float A = u.fb.bx[4][i];
                for (int j = i + 1 + tid; j < Mf; j += BLOCK) {
                    if (!u.fb.rem[j]) {
                        float ix1 = fmaxf(X1, u.fb.bx[0][j]), iy1 = fmaxf(Y1, u.fb.bx[1][j]);
                        float ix2 = fminf(X2, u.fb.bx[2][j]), iy2 = fminf(Y2, u.fb.bx[3][j]);
                        float iw = fmaxf(ix2 - ix1 + 1.f, 0.f);
                        float ih = fmaxf(iy2 - iy1 + 1.f, 0.f);
                        float inter = iw * ih;
                        if (inter / (A + u.fb.bx[4][j] - inter) > IOU_T) u.fb.rem[j] = 1;
                    }
                }
            }
            __syncthreads();
        }
        for (int i = tid; i < Mf; i += BLOCK) {
            if (!u.fb.rem[i]) {
                unsigned long long kk = u.fb.skey[i];
                unsigned int flat = (unsigned int)(c0 * R_N) + (~(unsigned int)kk);
                int p = atomicAdd(&g_count, 1);
                g_pool[p] = (kk & 0xffffffff00000000ULL) | (unsigned int)(~flat);
                g_pbox[flat] = make_float4(u.fb.bx[0][i], u.fb.bx[1][i], u.fb.bx[2][i], u.fb.bx[3][i]);
            }
        }
    }

    // ---------- ticket: last finisher runs phase C ----------
    __syncthreads();
    __threadfence();
    if (tid == 0) {
        int t = atomicAdd(&g_c2, 1);
        s_doC = (t == GRID - 1);
    }
    __syncthreads();
    if (!s_doC) return;
    __threadfence();

    // ---------- Phase C: shared-memory top-100 selection ----------
    int K = *(volatile int*)&g_count;
    bool smallK = (K <= SELCAP);
    if (smallK) {
        for (int i = tid; i < K; i += BLOCK) u.c.cand[i] = __ldcg(&g_pool[i]);
    }
    __syncthreads();

    int count = 0;
    if (K <= TOPK) {
        for (int i = tid; i < K; i += BLOCK) u.c.sel[i] = u.c.cand[i];
        count = K;
        __syncthreads();
    } else {
        // shared histogram over 2048 monotonic score bins
        #pragma unroll
        for (int q = 0; q < SELCAP / BLOCK; q++) u.c.hist[tid + q * BLOCK] = 0;
        __syncthreads();
        for (int i = tid; i < K; i += BLOCK) {
            unsigned long long k = smallK ? u.c.cand[i] : __ldcg(&g_pool[i]);
            atomicAdd(&u.c.hist[kbin(k)], 1);
        }
        __syncthreads();
        // 3-barrier suffix scan (4 bins/thread, shfl within warp, warp0 across warps)
        int base = tid * 4;
        int h0 = u.c.hist[base], h1 = u.c.hist[base + 1];
        int h2 = u.c.hist[base + 2], h3 = u.c.hist[base + 3];
        int cs = h0 + h1 + h2 + h3;
        int v = cs;
        #pragma unroll
        for (int off = 1; off < 32; off <<= 1) {
            int nv = __shfl_down_sync(0xffffffffu, v, off);
            if (lane + off < 32) v += nv;
        }
        if (lane == 0) wtot[wid] = v;
        __syncthreads();
        if (wid == 0) {
            int w = (lane < 16) ? wtot[lane] : 0;
            #pragma unroll
            for (int off = 1; off < 16; off <<= 1) {
                int nw = __shfl_down_sync(0xffffffffu, w, off);
                if (lane + off < 16) w += nw;
            }
            if (lane < 16) wtot[lane] = w;
        }
        __syncthreads();
        int S = v + ((wid < 15) ? wtot[wid + 1] : 0);   // keys with bin >= base
        int cum = S - cs;                                // keys with bin > base+3
        int hh[4] = {h0, h1, h2, h3};
        #pragma unroll
        for (int b = 3; b >= 0; b--) {
            int h = hh[b];
            if (cum < TOPK && cum + h >= TOPK) { s_thr = base + b; s_tot = cum + h; }
            cum += h;
        }
        __syncthreads();
        int thr = s_thr;
        if (s_tot <= SELCAP) {
            if (tid == 0) s_cnt = 0;
            __syncthreads();
            for (int i = tid; i < K; i += BLOCK) {
                unsigned long long k = smallK ? u.c.cand[i] : __ldcg(&g_pool[i]);
                if (kbin(k) >= thr) u.c.sel[atomicAdd(&s_cnt, 1)] = k;
            }
            __syncthreads();
            count = s_cnt;
        } else {
            // pathological ties: adaptive 64-bit radix descent on g_pool
            unsigned long long prefix = 0;
            int shift = 56, needed = TOPK;
            for (;;) {
                for (int i = tid; i < 256; i += BLOCK) u.c.hist[i] = 0;
                __syncthreads();
                for (int i = tid; i < K; i += BLOCK) {
                    unsigned long long k = __ldcg(&g_pool[i]);
                    bool act = (shift == 56) || ((k >> (shift + 8)) == prefix);
                    if (act) atomicAdd(&u.c.hist[(int)((k >> shift) & 255)], 1);
                }
                __syncthreads();
                if (tid == 0) {
                    int cum2 = 0, d;
                    for (d = 255; d > 0; d--) {
                        int h = u.c.hist[d];
                        if (cum2 + h >= needed) break;
                        cum2 += h;
                    }
                    s_d = d; s_cum = cum2; s_bin = u.c.hist[d];
                }
                __syncthreads();
                needed -= s_cum;
                prefix = (prefix << 8) | (unsigned int)s_d;
                int binCount = s_bin;
                shift -= 8;
                if ((TOPK - needed) + binCount <= CANDMAX || shift < 0) break;
                __syncthreads();
            }
            if (tid == 0) s_cnt = 0;
            __syncthreads();
            int sh = shift + 8;
            for (int i = tid; i < K; i += BLOCK) {
                unsigned long long k = __ldcg(&g_pool[i]);
                if ((k >> sh) >= prefix) {
                    int p = atomicAdd(&s_cnt, 1);
                    if (p < SELCAP) u.c.sel[p] = k;
                }
            }
            __syncthreads();
            count = min(s_cnt, SELCAP);
        }
    }

    // rank placement (keys unique -> exact ranks)
    for (int i = tid; i < count; i += BLOCK) {
        unsigned long long kk = u.c.sel[i];
        int rank = 0;
        for (int j = 0; j < count; j++) rank += (u.c.sel[j] > kk);
        if (rank < TOPK) {
            unsigned int flat = ~(unsigned int)(kk & 0xffffffffu);
            float score = unord32((unsigned int)(kk >> 32));
            int cc = flat / R_N;
            float4 b = g_pbox[flat];
            out[rank] = score;
            out[TOPK + 4 * rank + 0] = b.x;
            out[TOPK + 4 * rank + 1] = b.y;
            out[TOPK + 4 * rank + 2] = b.z;
            out[TOPK + 4 * rank + 3] = b.w;
            out[5 * TOPK + rank] = (float)(cc + 1);
        }
    }
    __syncthreads();
    if (count < TOPK && tid == 0) {
        // K < 100: fill remaining slots NEG-score, ascending unused flat idx
        int p = count;
        for (int f = 0; p < TOPK; f++) {
            bool used = false;
            for (int q = 0; q < count; q++) {
                unsigned int fl = ~(unsigned int)(u.c.sel[q] & 0xffffffffu);
                if ((int)fl == f) { used = true; break; }
            }
            if (!used) {
                int cc = f / R_N;
                int r = f - cc * R_N;
                float4 b = decode_box(props4, reg4, r, cc + 1, W, H);
                out[p] = NEGV;
                out[TOPK + 4 * p + 0] = b.x;
                out[TOPK + 4 * p + 1] = b.y;
                out[TOPK + 4 * p + 2] = b.z;
                out[TOPK + 4 * p + 3] = b.w;
                out[5 * TOPK + p] = (float)(cc + 1);
                p++;
            }
        }
    }

    // reset for next graph replay (only this block alive)
    __syncthreads();
    if (tid < NC) g_cnt[tid] = 0;
    if (tid == 0) { g_c1 = 0; g_c2 = 0; g_count = 0; }
    __threadfence();
}

// ---------------- launch ----------------
extern "C" void kernel_launch(void* const* d_in, const int* in_sizes, int n_in,
                              void* d_out, int out_size) {
    const float *logits = nullptr, *reg = nullptr, *props = nullptr;
    const void *pw = nullptr, *ph = nullptr;
    for (int i = 0; i < n_in; i++) {
        int s = in_sizes[i];
        if (s == R_N * C_N)            logits = (const float*)d_in[i];
        else if (s == R_N * C_N * 4)   reg    = (const float*)d_in[i];
        else if (s == R_N * 4)         props  = (const float*)d_in[i];
        else if (s == 1) { if (!pw) pw = d_in[i]; else ph = d_in[i]; }
    }
    k_fused<<<GRID, BLOCK>>>(logits, reg, props, pw, ph, (float*)d_out);
}

// round 10
// speedup vs baseline: 1.5663x; 1.4015x over previous
#include <cuda_runtime.h>

#define R_N 1000
#define C_N 81
#define NC  80          // foreground classes == grid size
#define NEGV (-1e9f)
#define SCORE_T 0.05f
#define IOU_T 0.5f
#define TOPK 100
#define GRID NC
#define BLOCK 512
#define SELCAP 2048
#define CANDMAX 512

// ---------------- device scratch (no allocations allowed) ----------------
__device__ int g_cnt[NC];                          // per-class pre-NMS counts
__device__ unsigned long long g_clist[NC * R_N];   // per-class key lists
__device__ unsigned long long g_pool[NC * R_N];    // post-NMS survivor keys
__device__ float4 g_pbox[NC * R_N];                // survivor boxes by flat idx
__device__ int g_count;
__device__ int g_c1, g_c2;                         // barrier / ticket counters

// ---------------- helpers ----------------
__device__ __forceinline__ unsigned int ord32(float f) {
    unsigned int u = __float_as_uint(f);
    return (u & 0x80000000u) ? ~u : (u | 0x80000000u);
}
__device__ __forceinline__ float unord32(unsigned int u) {
    unsigned int b = (u & 0x80000000u) ? (u ^ 0x80000000u) : ~u;
    return __uint_as_float(b);
}
__device__ __forceinline__ float load_dim(const void* p) {
    int iv = *(const int*)p;
    if (iv > 0 && iv < 1000000) return (float)iv;   // passed as int
    return *(const float*)p;                         // passed as float
}
__device__ __forceinline__ void push_key(int c, int row, float prob) {
    // c in 1..80 (pre-NMS per-class list)
    if (prob > SCORE_T) {
        int slot = atomicAdd(&g_cnt[c - 1], 1);
        g_clist[(c - 1) * R_N + slot] =
            ((unsigned long long)ord32(prob) << 32) | (unsigned int)(~row);
    }
}
// monotone 11-bit score bin (key bits 51..61; bits 62..63 constant for 0<score<2)
__device__ __forceinline__ int kbin(unsigned long long k) {
    return (int)(k >> 51) & (SELCAP - 1);
}

// decode + clip one box (class c in [1,80], row r) — exact reference math
__device__ __forceinline__ float4 decode_box(const float4* __restrict__ props4,
                                             const float4* __restrict__ reg4,
                                             int r, int c, float W, float H) {
    const float CLIPV = 4.135166556742356f;   // log(1000/16)
    float4 p = props4[r];
    float bw = p.z - p.x + 1.f, bh = p.w - p.y + 1.f;
    float cx = p.x + 0.5f * bw,  cy = p.y + 0.5f * bh;
    float4 rr = reg4[(size_t)r * C_N + c];
    float dx = rr.x / 10.0f;
    float dy = rr.y / 10.0f;
    float dw = fminf(rr.z / 5.0f, CLIPV);
    float dh = fminf(rr.w / 5.0f, CLIPV);
    float pcx = dx * bw + cx;
    float pcy = dy * bh + cy;
    float pw2 = expf(dw) * bw;
    float ph2 = expf(dh) * bh;
    float x1 = fminf(fmaxf(pcx - 0.5f * pw2, 0.f), W - 1.f);
    float y1 = fminf(fmaxf(pcy - 0.5f * ph2, 0.f), H - 1.f);
    float x2 = fminf(fmaxf(pcx + 0.5f * pw2 - 1.f, 0.f), W - 1.f);
    float y2 = fminf(fmaxf(pcy + 0.5f * ph2 - 1.f, 0.f), H - 1.f);
    return make_float4(x1, y1, x2, y2);
}

// shared scratch (phases temporally disjoint)
union Scratch {
    struct {                                  // phase B
        unsigned long long skey[1024];
        float sx1[1024], sy1[1024], sx2[1024], sy2[1024], sar[1024];
        unsigned char srem[1024];
        unsigned long long smask[64];
        unsigned long long keep;
    } b;
    struct {                                  // phase C
        unsigned long long cand[SELCAP];
        int hist[SELCAP];
        unsigned long long sel[CANDMAX];
    } c;
};

__device__ void bitonic_desc(unsigned long long* a, int n) {
    for (unsigned int k = 2; k <= (unsigned int)n; k <<= 1) {
        for (unsigned int j = k >> 1; j > 0; j >>= 1) {
            for (unsigned int i = threadIdx.x; i < (unsigned int)n; i += BLOCK) {
                unsigned int l = i ^ j;
                if (l > i) {
                    unsigned long long x = a[i], y = a[l];
                    bool up = ((i & k) == 0);
                    if (up ? (x < y) : (x > y)) { a[i] = y; a[l] = x; }
                }
            }
            __syncthreads();
        }
    }
}

// ---------------- the single fused kernel ----------------
__global__ void __launch_bounds__(BLOCK) k_fused(
        const float* __restrict__ logits,
        const float* __restrict__ reg,
        const float* __restrict__ props,
        const void* pw, const void* ph,
        float* __restrict__ out) {

    __shared__ Scratch u;
    __shared__ int wtot[16];
    __shared__ int s_cnt, s_thr, s_tot, s_doC, s_d, s_cum, s_bin;

    int tid = threadIdx.x;
    int wid = tid >> 5;
    int lane = tid & 31;
    const float4* props4 = (const float4*)props;
    const float4* reg4 = (const float4*)reg;
    float W = load_dim(pw), H = load_dim(ph);

    // ---------- Phase A: softmax stats + score filter + per-class push (as R6) ----------
    {
        int row = blockIdx.x * (BLOCK / 32) + wid;   // one warp per row, contiguous
        if (row < R_N) {
            const float* lg = logits + (size_t)row * C_N;
            float a = (lane      < C_N) ? lg[lane]      : -INFINITY;
            float b = (lane + 32 < C_N) ? lg[lane + 32] : -INFINITY;
            float d = (lane + 64 < C_N) ? lg[lane + 64] : -INFINITY;
            float m = fmaxf(a, fmaxf(b, d));
            for (int o = 16; o; o >>= 1) m = fmaxf(m, __shfl_xor_sync(0xffffffffu, m, o));
            float ea = (lane      < C_N) ? expf(a - m) : 0.f;
            float eb = (lane + 32 < C_N) ? expf(b - m) : 0.f;
            float ed = (lane + 64 < C_N) ? expf(d - m) : 0.f;
            float s = ea + eb + ed;
            for (int o = 16; o; o >>= 1) s += __shfl_xor_sync(0xffffffffu, s, o);
            float inv = 1.f / s;
            if (lane >= 1)  push_key(lane,      row, ea * inv);   // c = 1..31
            push_key(lane + 32, row, eb * inv);                   // c = 32..63
            if (lane <= 16) push_key(lane + 64, row, ed * inv);   // c = 64..80
        }
    }
    __syncthreads();
    __threadfence();
    if (tid == 0) {
        atomicAdd(&g_c1, 1);
        while (*(volatile int*)&g_c1 < GRID) __nanosleep(32);   // all 80 blocks resident
    }
    __syncthreads();
    __threadfence();

    // ---------- Phase B: per-class NMS on pre-filtered list (as R6) ----------
    int c0 = blockIdx.x;
    int c = c0 + 1;
    int M = *(volatile int*)&g_cnt[c0];

    if (M > 0 && M <= 64) {
        if (tid < M) u.b.skey[tid] = __ldcg(&g_clist[c0 * R_N + tid]);
        __syncthreads();
        unsigned long long mykey = 0ULL;
        float4 b;
        float A = 0.f;
        int rank = 0;
        if (tid < M) {
            mykey = u.b.skey[tid];
            for (int j = 0; j < M; j++) rank += (u.b.skey[j] > mykey);
            int r = (int)(~(unsigned int)mykey);
            b = decode_box(props4, reg4, r, c, W, H);
            A = (b.z - b.x + 1.f) * (b.w - b.y + 1.f);
            u.b.sx1[rank] = b.x; u.b.sy1[rank] = b.y;
            u.b.sx2[rank] = b.z; u.b.sy2[rank] = b.w;
            u.b.sar[rank] = A;
        }
        __syncthreads();
        if (tid < M) {
            unsigned long long msk = 0ULL;
            for (int j = rank + 1; j < M; j++) {
                float ix1 = fmaxf(b.x, u.b.sx1[j]), iy1 = fmaxf(b.y, u.b.sy1[j]);
                float ix2 = fminf(b.z, u.b.sx2[j]), iy2 = fminf(b.w, u.b.sy2[j]);
                float iw = fmaxf(ix2 - ix1 + 1.f, 0.f);
                float ih = fmaxf(iy2 - iy1 + 1.f, 0.f);
                float inter = iw * ih;
                float iou = inter / (A + u.b.sar[j] - inter);
                if (iou > IOU_T) msk |= (1ULL << j);
            }
            u.b.smask[rank] = msk;
        }
        __syncthreads();
        if (tid == 0) {
            unsigned long long removed = 0ULL, keep = 0ULL;
            for (int i = 0; i < M; i++)
                if (!((removed >> i) & 1ULL)) { keep |= (1ULL << i); removed |= u.b.smask[i]; }
            u.b.keep = keep;
        }
        __syncthreads();
        if (tid < M && ((u.b.keep >> rank) & 1ULL)) {
            unsigned int r = ~(unsigned int)mykey;
            unsigned int flat = (unsigned int)(c0 * R_N) + r;
            int p = atomicAdd(&g_count, 1);
            g_pool[p] = (mykey & 0xffffffff00000000ULL) | (unsigned int)(~flat);
            g_pbox[flat] = b;
        }
    } else if (M > 64) {
        // fallback: sorted serial greedy (rare)
        int Mf = min(M, 1024);
        for (int i = tid; i < Mf; i += BLOCK) u.b.skey[i] = __ldcg(&g_clist[c0 * R_N + i]);
        int n = 1; while (n < Mf) n <<= 1;
        for (int i = Mf + tid; i < n; i += BLOCK) u.b.skey[i] = 0ULL;
        __syncthreads();
        bitonic_desc(u.b.skey, n);
        for (int i = tid; i < Mf; i += BLOCK) {
            int r = (int)(~(unsigned int)u.b.skey[i]);
            float4 b = decode_box(props4, reg4, r, c, W, H);
            u.b.sx1[i] = b.x; u.b.sy1[i] = b.y; u.b.sx2[i] = b.z; u.b.sy2[i] = b.w;
            u.b.sar[i] = (b.z - b.x + 1.f) * (b.w - b.y + 1.f);
            u.b.srem[i] = 0;
        }
        __syncthreads();
        for (int i = 0; i < Mf; i++) {
            if (!u.b.srem[i]) {
                float X1 = u.b.sx1[i], Y1 = u.b.sy1[i], X2 = u.b.sx2[i], Y2 = u.b.sy2[i];
                float A = u.b.sar[i];
                for (int j = i + 1 + tid; j < Mf; j += BLOCK) {
                    if (!u.b.srem[j]) {
                        float ix1 = fmaxf(X1, u.b.sx1[j]), iy1 = fmaxf(Y1, u.b.sy1[j]);
                        float ix2 = fminf(X2, u.b.sx2[j]), iy2 = fminf(Y2, u.b.sy2[j]);
                        float iw = fmaxf(ix2 - ix1 + 1.f, 0.f);
                        float ih = fmaxf(iy2 - iy1 + 1.f, 0.f);
                        float inter = iw * ih;
                        if (inter / (A + u.b.sar[j] - inter) > IOU_T) u.b.srem[j] = 1;
                    }
                }
            }
            __syncthreads();
        }
        for (int i = tid; i < Mf; i += BLOCK) {
            if (!u.b.srem[i]) {
                unsigned long long kk = u.b.skey[i];
                unsigned int r = ~(unsigned int)kk;
                unsigned int flat = (unsigned int)(c0 * R_N) + r;
                int p = atomicAdd(&g_count, 1);
                g_pool[p] = (kk & 0xffffffff00000000ULL) | (unsigned int)(~flat);
                g_pbox[flat] = make_float4(u.b.sx1[i], u.b.sy1[i], u.b.sx2[i], u.b.sy2[i]);
            }
        }
    }

    // ---------- ticket: last block to finish B runs phase C ----------
    __syncthreads();
    __threadfence();
    if (tid == 0) {
        int t = atomicAdd(&g_c2, 1);
        s_doC = (t == GRID - 1);
    }
    __syncthreads();
    if (!s_doC) return;
    __threadfence();

    // ---------- Phase C: shared-hist threshold + rank placement ----------
    int K = *(volatile int*)&g_count;
    int count = 0;

    if (K <= TOPK) {
        for (int i = tid; i < K; i += BLOCK) u.c.sel[i] = __ldcg(&g_pool[i]);
        count = K;
        __syncthreads();
    } else {
        bool smallK = (K <= SELCAP);
        if (smallK) for (int i = tid; i < K; i += BLOCK) u.c.cand[i] = __ldcg(&g_pool[i]);
        #pragma unroll
        for (int q = 0; q < SELCAP / BLOCK; q++) u.c.hist[tid + q * BLOCK] = 0;
        __syncthreads();
        for (int i = tid; i < K; i += BLOCK) {
            unsigned long long k = smallK ? u.c.cand[i] : __ldcg(&g_pool[i]);
            atomicAdd(&u.c.hist[kbin(k)], 1);
        }
        __syncthreads();
        // 3-barrier warp-shfl suffix scan over 2048 bins (4 bins/thread)
        int base = tid * 4;
        int h0 = u.c.hist[base], h1 = u.c.hist[base + 1];
        int h2 = u.c.hist[base + 2], h3 = u.c.hist[base + 3];
        int cs = h0 + h1 + h2 + h3;
        int v = cs;
        #pragma unroll
        for (int off = 1; off < 32; off <<= 1) {
            int nv = __shfl_down_sync(0xffffffffu, v, off);
            if (lane + off < 32) v += nv;
        }
        if (lane == 0) wtot[wid] = v;
        __syncthreads();
        if (wid == 0) {
            int w = (lane < 16) ? wtot[lane] : 0;
            #pragma unroll
            for (int off = 1; off < 16; off <<= 1) {
                int nw = __shfl_down_sync(0xffffffffu, w, off);
                if (lane + off < 16) w += nw;
            }
            if (lane < 16) wtot[lane] = w;   // suffix over warps lane..15
        }
        __syncthreads();
        int S = v + ((wid < 15) ? wtot[wid + 1] : 0);   // keys with bin >= base
        int cum = S - cs;                                // keys with bin > base+3
        int hh[4] = {h0, h1, h2, h3};
        #pragma unroll
        for (int b = 3; b >= 0; b--) {
            int h = hh[b];
            if (cum < TOPK && cum + h >= TOPK) { s_thr = base + b; s_tot = cum + h; }
            cum += h;
        }
        __syncthreads();
        int thr = s_thr;
        if (s_tot <= CANDMAX) {
            if (tid == 0) s_cnt = 0;
            __syncthreads();
            for (int i = tid; i < K; i += BLOCK) {
                unsigned long long k = smallK ? u.c.cand[i] : __ldcg(&g_pool[i]);
                if (kbin(k) >= thr) u.c.sel[atomicAdd(&s_cnt, 1)] = k;
            }
            __syncthreads();
            count = s_cnt;
        } else {
            // pathological ties: adaptive 64-bit radix descent on g_pool
            unsigned long long prefix = 0;
            int shift = 56, needed = TOPK;
            for (;;) {
                for (int i = tid; i < 256; i += BLOCK) u.c.hist[i] = 0;
                __syncthreads();
                for (int i = tid; i < K; i += BLOCK) {
                    unsigned long long k = __ldcg(&g_pool[i]);
                    bool act = (shift == 56) || ((k >> (shift + 8)) == prefix);
                    if (act) atomicAdd(&u.c.hist[(int)((k >> shift) & 255)], 1);
                }
                __syncthreads();
                if (tid == 0) {
                    int cum2 = 0, d;
                    for (d = 255; d > 0; d--) {
                        int h = u.c.hist[d];
                        if (cum2 + h >= needed) break;
                        cum2 += h;
                    }
                    s_d = d; s_cum = cum2; s_bin = u.c.hist[d];
                }
                __syncthreads();
                needed -= s_cum;
                prefix = (prefix << 8) | (unsigned int)s_d;
                int binCount = s_bin;
                shift -= 8;
                if ((TOPK - needed) + binCount <= CANDMAX || shift < 0) break;
                __syncthreads();
            }
            if (tid == 0) s_cnt = 0;
            __syncthreads();
            int sh = shift + 8;
            for (int i = tid; i < K; i += BLOCK) {
                unsigned long long k = __ldcg(&g_pool[i]);
                if ((k >> sh) >= prefix) {
                    int p = atomicAdd(&s_cnt, 1);
                    if (p < CANDMAX) u.c.sel[p] = k;
                }
            }
            __syncthreads();
            count = min(s_cnt, CANDMAX);
        }
    }

    // rank placement (keys unique -> exact ranks)
    for (int i = tid; i < count; i += BLOCK) {
        unsigned long long kk = u.c.sel[i];
        int rank = 0;
        for (int j = 0; j < count; j++) rank += (u.c.sel[j] > kk);
        if (rank < TOPK) {
            unsigned int flat = ~(unsigned int)(kk & 0xffffffffu);
            float score = unord32((unsigned int)(kk >> 32));
            int cc = flat / R_N;
            float4 b = g_pbox[flat];
            out[rank] = score;
            out[TOPK + 4 * rank + 0] = b.x;
            out[TOPK + 4 * rank + 1] = b.y;
            out[TOPK + 4 * rank + 2] = b.z;
            out[TOPK + 4 * rank + 3] = b.w;
            out[5 * TOPK + rank] = (float)(cc + 1);
        }
    }
    __syncthreads();
    if (count < TOPK && tid == 0) {
        // K < 100: fill remaining slots NEG-score, ascending unused flat idx
        int p = count;
        for (int f = 0; p < TOPK; f++) {
            bool used = false;
            for (int q = 0; q < count; q++) {
                unsigned int fl = ~(unsigned int)(u.c.sel[q] & 0xffffffffu);
                if ((int)fl == f) { used = true; break; }
            }
            if (!used) {
                int cc = f / R_N;
                int r = f - cc * R_N;
                float4 b = decode_box(props4, reg4, r, cc + 1, W, H);
                out[p] = NEGV;
                out[TOPK + 4 * p + 0] = b.x;
                out[TOPK + 4 * p + 1] = b.y;
                out[TOPK + 4 * p + 2] = b.z;
                out[TOPK + 4 * p + 3] = b.w;
                out[5 * TOPK + p] = (float)(cc + 1);
                p++;
            }
        }
    }

    // reset for next graph replay (only this block alive)
    __syncthreads();
    if (tid < NC) g_cnt[tid] = 0;
    if (tid == 0) { g_c1 = 0; g_c2 = 0; g_count = 0; }
    __threadfence();
}

// ---------------- launch ----------------
extern "C" void kernel_launch(void* const* d_in, const int* in_sizes, int n_in,
                              void* d_out, int out_size) {
    const float *logits = nullptr, *reg = nullptr, *props = nullptr;
    const void *pw = nullptr, *ph = nullptr;
    for (int i = 0; i < n_in; i++) {
        int s = in_sizes[i];
        if (s == R_N * C_N)            logits = (const float*)d_in[i];
        else if (s == R_N * C_N * 4)   reg    = (const float*)d_in[i];
        else if (s == R_N * 4)         props  = (const float*)d_in[i];
        else if (s == 1) { if (!pw) pw = d_in[i]; else ph = d_in[i]; }
    }
    k_fused<<<GRID, BLOCK>>>(logits, reg, props, pw, ph, (float*)d_out);
}